// round 17
// baseline (speedup 1.0000x reference)
#include <cuda_runtime.h>
#include <math_constants.h>

// StratifiedMaxPooling: out[b,c] = max_{j: labels[j]==c} values[b,j]
// values: [B=128, N=200000] f32, labels: [N] int32, C=100.
//
// R17 = R16's static-schedule pool kernel (measured ~29-30us) with the
// 15.5us reduce_kernel tail replaced by the proven in-kernel atomic flush:
// per-block partials -> atomicMax(ukey) over 12800 addresses, last-arriving
// block decodes to out and self-resets for graph replay. Single kernel.
//
// Pool design (unchanged from R16):
//  - 148 blocks (1/SM) x 512 thr = 4 rowgroups x 4 streams; block covers all
//    128 rows; 32-column tiles.
//  - Stream s owns FIXED cols 8s..8s+7 (unrolled x8, branch-free, perfectly
//    balanced). Cross-stream same-class races killed by 4 acc copies
//    acc[s][row][class]; within a stream same warp+lane updates in program
//    order => race-free. No ballot/ffs/match anywhere.
//  - Bank-conflict-free: stage [col][row] pitch 129, acc pitch 101.

#define FULL 0xFFFFFFFFu

static const int NBLK   = 148;
static const int NTHR   = 512;          // 16 warps
static const int C_NUM  = 100;
static const int C_PAD  = 101;
static const int B_NUM  = 128;
static const int NOUT   = B_NUM * C_NUM;      // 12800
static const int TILE   = 32;                 // columns per tile
static const int RPITCH = 129;                // stage row pitch
static const int ACC_STRIDE = B_NUM * C_PAD;  // 12928 floats per copy
static const int STG_F  = TILE * RPITCH;      // 4128 floats

__device__ unsigned g_keys[NOUT];  // zero static init; self-cleaning
__device__ unsigned g_done;        // zero static init; self-cleaning

// Monotonic float -> unsigned key; ukey(any finite or -inf) > 0, so the
// zero-initialized g_keys is a valid "empty" identity for atomicMax.
__device__ __forceinline__ unsigned ukey(float f) {
    int x = __float_as_int(f);
    return (unsigned)(x ^ ((x >> 31) | 0x80000000));
}
__device__ __forceinline__ float udecode(unsigned u) {
    unsigned m = ((int)u < 0) ? 0x80000000u : 0xFFFFFFFFu;
    return __int_as_float((int)(u ^ m));
}

__global__ __launch_bounds__(NTHR, 1)
void pool_kernel(const float* __restrict__ values,
                 const int*   __restrict__ labels,
                 float* __restrict__ out, int N, int ntiles)
{
    extern __shared__ __align__(16) float sdyn[];
    float* const acc   = sdyn;                       // [4][ACC_STRIDE]
    float* const stage = sdyn + 4 * ACC_STRIDE;      // [TILE][RPITCH]
    int*   const scl   = (int*)(stage + STG_F);      // [TILE]
    __shared__ int s_last;

    const int tid  = threadIdx.x;
    const int lane = tid & 31;
    const int warp = tid >> 5;
    const int rg   = warp & 3;          // rowgroup 0..3 (32 rows each)
    const int s    = warp >> 2;         // stream 0..3 (8 cols each)
    const int row  = rg * 32 + lane;

    for (int i = tid; i < 4 * ACC_STRIDE; i += NTHR) acc[i] = -CUDART_INF_F;

    // ---- fill mapping: thread -> rows {frow, frow+64}, col-quad q
    const int frow = tid >> 3;          // 0..63
    const int q    = tid & 7;           // quad: cols 4q..4q+3
    const float* const v0p = values + (size_t)frow * N + 4 * q;
    const float* const v1p = values + (size_t)(frow + 64) * N + 4 * q;
    float* const sfill = stage + (4 * q) * RPITCH + frow;

    // ---- process mapping
    float* const accrow = acc + s * ACC_STRIDE + row * C_PAD;
    const float* const strow = stage + row;
    const int cbase = 8 * s;            // my 8 fixed columns

    // ---- prefetch tile t0 into registers
    int t = blockIdx.x;
    float4 a0, a1;
    int lb = 0;
    {
        a0 = __ldcs(reinterpret_cast<const float4*>(v0p + (size_t)t * TILE));
        a1 = __ldcs(reinterpret_cast<const float4*>(v1p + (size_t)t * TILE));
        if (tid < TILE) lb = labels[t * TILE + tid];
    }

    while (true) {
        __syncthreads();   // previous tile processed (and acc init done)

        // fill stage from prefetched registers
        sfill[0]          = a0.x;
        sfill[RPITCH]     = a0.y;
        sfill[2 * RPITCH] = a0.z;
        sfill[3 * RPITCH] = a0.w;
        float* sf1 = sfill + 64;
        sf1[0]          = a1.x;
        sf1[RPITCH]     = a1.y;
        sf1[2 * RPITCH] = a1.z;
        sf1[3 * RPITCH] = a1.w;
        if (tid < TILE) scl[tid] = lb;

        // prefetch next tile (overlaps the process phase below)
        const int tn = t + NBLK;
        const bool hn = tn < ntiles;
        if (hn) {
            a0 = __ldcs(reinterpret_cast<const float4*>(v0p + (size_t)tn * TILE));
            a1 = __ldcs(reinterpret_cast<const float4*>(v1p + (size_t)tn * TILE));
            if (tid < TILE) lb = labels[tn * TILE + tid];
        }

        __syncthreads();   // stage + scl ready

        // process my 8 fixed columns, fully unrolled, branch-free
#pragma unroll
        for (int j = 0; j < 8; j++) {
            const int c = cbase + j;
            const int k = scl[c];                  // broadcast LDS
            const float x = strow[c * RPITCH];     // conflict-free LDS
            float* const a = accrow + k;
            *a = fmaxf(*a, x);                     // same-lane ordered RMW
        }

        if (!hn) break;
        t = tn;
    }

    __syncthreads();   // all streams/rowgroups done

    // ---- merge 4 copies + atomic flush (rotated to stagger same-address)
    {
        const int rot = (blockIdx.x * 1051) % NOUT;
        for (int i = tid; i < NOUT; i += NTHR) {
            int i2 = i + rot;
            if (i2 >= NOUT) i2 -= NOUT;
            const int r = i2 / C_NUM;
            const int c = i2 - r * C_NUM;
            const int o = r * C_PAD + c;
            float m = fmaxf(fmaxf(acc[o], acc[ACC_STRIDE + o]),
                            fmaxf(acc[2 * ACC_STRIDE + o],
                                  acc[3 * ACC_STRIDE + o]));
            atomicMax(&g_keys[i2], ukey(m));
        }
    }
    __threadfence();
    __syncthreads();
    if (tid == 0)
        s_last = (atomicAdd(&g_done, 1u) == (unsigned)(gridDim.x - 1));
    __syncthreads();

    // ---- last block: decode to output, self-reset for graph replays
    if (s_last) {
        for (int i = tid; i < NOUT; i += NTHR) {
            out[i] = udecode(__ldcg(&g_keys[i]));
            g_keys[i] = 0u;
        }
        __threadfence();
        if (tid == 0) g_done = 0u;
    }
}

extern "C" void kernel_launch(void* const* d_in, const int* in_sizes, int n_in,
                              void* d_out, int out_size)
{
    const float* values = (const float*)d_in[0];
    const int*   labels = (const int*)d_in[1];
    const int N = in_sizes[1];          // 200000
    const int ntiles = N / TILE;        // 6250 exact

    const int dyn_bytes = (4 * ACC_STRIDE + STG_F) * (int)sizeof(float)
                        + TILE * (int)sizeof(int);   // 223,488 B
    cudaFuncSetAttribute(pool_kernel,
                         cudaFuncAttributeMaxDynamicSharedMemorySize,
                         dyn_bytes);

    pool_kernel<<<NBLK, NTHR, dyn_bytes>>>(values, labels, (float*)d_out,
                                           N, ntiles);
}